// round 12
// baseline (speedup 1.0000x reference)
#include <cuda_runtime.h>

#define B_ROWS 8192
#define P_ROWS 1024
#define D_DIM  256
#define NPART  32          // producer blocks (32 proto rows each)
#define GRID   512         // 256 thr, <=64 regs, 4/SM -> all resident (barrier-safe)
#define ROWS_PER_BLK (B_ROWS / GRID)   // 16: 8 warps * 2 rows

// Device-global scratch (allocation-free rule), zero-initialized at load.
__device__ float g_partial[NPART * D_DIM];   // per-producer column sums
__device__ float g_p2[NPART];                // per-producer sum of squares
__device__ float g_m2[D_DIM];                // FINAL 2*mean_p proto[:,d]
__device__ float g_c;                        // FINAL mean_p ||p||^2
__device__ unsigned int g_count = 0;         // producer arrivals (32)
__device__ unsigned int g_ready = 0;         // m2/c published flag
__device__ unsigned int g_done  = 0;         // exit counter (replay reset)

__device__ __forceinline__ unsigned int ld_acq_u32(const unsigned int* p) {
    unsigned int v;
    asm volatile("ld.acquire.gpu.global.u32 %0, [%1];" : "=r"(v) : "l"(p) : "memory");
    return v;
}
__device__ __forceinline__ void st_rel_u32(unsigned int* p, unsigned int v) {
    asm volatile("st.release.gpu.global.u32 [%0], %1;" :: "l"(p), "r"(v) : "memory");
}

__global__ void __launch_bounds__(256, 4)
som_fused(const float* __restrict__ x,
          const float* __restrict__ proto,
          float* __restrict__ out) {
    const int tid  = threadIdx.x;
    const int lane = tid & 31;
    const int warp = tid >> 5;
    const int blk  = blockIdx.x;

    // ---- x loads first: 4 independent fully-coalesced LDG.128 per thread -----
    // lane L covers d in [4L,4L+4) and [128+4L,...): 512B per warp-LDG.
    const int row0 = blk * ROWS_PER_BLK + warp * 2;
    const float* r0p = x + row0 * D_DIM + lane * 4;
    const float* r1p = r0p + D_DIM;
    float4 a0 = *reinterpret_cast<const float4*>(r0p);
    float4 a1 = *reinterpret_cast<const float4*>(r0p + 128);
    float4 b0 = *reinterpret_cast<const float4*>(r1p);
    float4 b1 = *reinterpret_cast<const float4*>(r1p + 128);

    __shared__ __align__(16) float sg[4 * D_DIM];
    __shared__ float sp[8];
    __shared__ unsigned int sm_role;

    // ---- Producers (blocks 0..31): prototype partials -----------------------
    if (blk < NPART) {
        const int c4   = tid & 63;           // float4 column group
        const int g    = tid >> 6;           // 4 row-groups of 8 rows
        const int prow = blk * (P_ROWS / NPART) + g * 8;

        float4 s = make_float4(0.f, 0.f, 0.f, 0.f);
        float sq = 0.f;
#pragma unroll
        for (int r = 0; r < 8; ++r) {        // 8 more independent LDG.128
            float4 v = *reinterpret_cast<const float4*>(
                proto + (prow + r) * D_DIM + c4 * 4);
            s.x += v.x; s.y += v.y; s.z += v.z; s.w += v.w;
            sq  += v.x * v.x + v.y * v.y + v.z * v.z + v.w * v.w;
        }
        *reinterpret_cast<float4*>(&sg[g * D_DIM + c4 * 4]) = s;
#pragma unroll
        for (int o = 16; o > 0; o >>= 1)
            sq += __shfl_down_sync(0xFFFFFFFFu, sq, o);
        if (lane == 0) sp[warp] = sq;
        __syncthreads();

        g_partial[blk * D_DIM + tid] =
            sg[tid] + sg[D_DIM + tid] + sg[2 * D_DIM + tid] + sg[3 * D_DIM + tid];
        if (tid == 0) {
            float p2 = 0.f;
#pragma unroll
            for (int i = 0; i < 8; ++i) p2 += sp[i];
            g_p2[blk] = p2;
        }

        __threadfence();                     // EVERY thread fences its stores (R6)
        __syncthreads();
        if (tid == 0) {
            unsigned int old = atomicAdd(&g_count, 1u);
            sm_role = (old == NPART - 1) ? 1u : 0u;
        }
        __syncthreads();

        // Last producer: combine 32 partials -> FINAL g_m2/g_c, publish flag.
        if (sm_role) {
            __threadfence();                 // acquire side of the arrivals
            float s2 = 0.f;
#pragma unroll
            for (int i = 0; i < NPART; ++i)  // 32 L2-hit loads, MLP=32
                s2 += __ldcg(&g_partial[i * D_DIM + tid]);
            g_m2[tid] = s2 * (2.0f / (float)P_ROWS);
            if (warp == 0) {
                float v = __ldcg(&g_p2[lane]);
#pragma unroll
                for (int o = 16; o > 0; o >>= 1)
                    v += __shfl_down_sync(0xFFFFFFFFu, v, o);
                if (lane == 0) g_c = v * (1.0f / (float)P_ROWS);
            }
            __threadfence();                 // m2/c visible before flag
            __syncthreads();
            if (tid == 0) st_rel_u32(&g_ready, 1u);
        }
    }

    // ---- Pre-barrier: the x^2 half of the result (no proto dependency) -------
    float sq0 = a0.x * a0.x + a0.y * a0.y + a0.z * a0.z + a0.w * a0.w
              + a1.x * a1.x + a1.y * a1.y + a1.z * a1.z + a1.w * a1.w;
    float sq1 = b0.x * b0.x + b0.y * b0.y + b0.z * b0.z + b0.w * b0.w
              + b1.x * b1.x + b1.y * b1.y + b1.z * b1.z + b1.w * b1.w;
#pragma unroll
    for (int o = 16; o > 0; o >>= 1) {
        sq0 += __shfl_down_sync(0xFFFFFFFFu, sq0, o);
        sq1 += __shfl_down_sync(0xFFFFFFFFu, sq1, o);
    }

    // ---- Barrier: wait for published m2/c ------------------------------------
    if (tid == 0) {
        while (ld_acq_u32(&g_ready) == 0u) { }
    }
    __syncthreads();

    // ---- Post-barrier tail: 2 L2 loads, 8 FMAs, reduce, store ----------------
    const float4 m0 = __ldcg(reinterpret_cast<const float4*>(&g_m2[lane * 4]));
    const float4 m1 = __ldcg(reinterpret_cast<const float4*>(&g_m2[128 + lane * 4]));
    const float  c  = __ldcg(&g_c);

    float d0 = a0.x * m0.x + a0.y * m0.y + a0.z * m0.z + a0.w * m0.w
             + a1.x * m1.x + a1.y * m1.y + a1.z * m1.z + a1.w * m1.w;
    float d1 = b0.x * m0.x + b0.y * m0.y + b0.z * m0.z + b0.w * m0.w
             + b1.x * m1.x + b1.y * m1.y + b1.z * m1.z + b1.w * m1.w;
#pragma unroll
    for (int o = 16; o > 0; o >>= 1) {
        d0 += __shfl_down_sync(0xFFFFFFFFu, d0, o);
        d1 += __shfl_down_sync(0xFFFFFFFFu, d1, o);
    }
    if (lane == 0) {
        out[row0]     = sq0 - d0 + c;
        out[row0 + 1] = sq1 - d1 + c;
    }

    // ---- Replay-state reset (measured ~free; keeps launches stateless) -------
    __syncthreads();
    __shared__ unsigned int sm_last;
    if (tid == 0) {
        unsigned int d = atomicAdd(&g_done, 1u);
        sm_last = (d == GRID - 1) ? 1u : 0u;
    }
    __syncthreads();
    if (sm_last && tid == 0) {
        g_count = 0;
        g_ready = 0;
        g_done  = 0;
        __threadfence();
    }
}

extern "C" void kernel_launch(void* const* d_in, const int* in_sizes, int n_in,
                              void* d_out, int out_size) {
    const float* x     = (const float*)d_in[0];  // (8192, 256) float32
    const float* proto = (const float*)d_in[1];  // (1024, 256) float32
    float* out = (float*)d_out;                  // (8192,) float32

    som_fused<<<GRID, 256>>>(x, proto, out);
}

// round 13
// speedup vs baseline: 1.1662x; 1.1662x over previous
#include <cuda_runtime.h>

#define B_ROWS 8192
#define P_ROWS 1024
#define D_DIM  256
#define NPART  64          // producer blocks, 16 proto rows each (R3 config)
#define GRID   592         // 148 SMs * 4 resident blocks @256thr -> barrier-safe
#define NWARP  8

// Device-global scratch (allocation-free rule), zero-initialized at load.
__device__ float g_partial[NPART * D_DIM];   // per-producer column sums
__device__ float g_p2[NPART];                // per-producer sum of squares
__device__ unsigned int g_count = 0;         // producer arrivals
__device__ unsigned int g_done  = 0;         // exit counter (replay reset)

__device__ __forceinline__ unsigned int ld_acq_u32(const unsigned int* p) {
    unsigned int v;
    asm volatile("ld.acquire.gpu.global.u32 %0, [%1];" : "=r"(v) : "l"(p) : "memory");
    return v;
}

__global__ void __launch_bounds__(256, 4)
som_fused(const float* __restrict__ x,
          const float* __restrict__ proto,
          float* __restrict__ out) {
    const int tid  = threadIdx.x;
    const int lane = tid & 31;
    const int warp = tid >> 5;
    const int blk  = blockIdx.x;

    __shared__ __align__(16) float sm_grp[4 * D_DIM];  // proto row-group partials
    __shared__ __align__(16) float sm_m2[D_DIM];       // combined 2*mean vector
    __shared__ float sm_p2g[NWARP];
    __shared__ float sm_c;

    // ---- Phase 1: prototype partials (blocks 0..63, 16 rows each) ------------
    // Proto loads are the FIRST memory ops on producer blocks (critical path).
    if (blk < NPART) {
        const int c4   = tid & 63;           // float4 column group
        const int g    = tid >> 6;           // 4 row-groups of 4 rows
        const int row0 = blk * (P_ROWS / NPART) + g * 4;

        float4 s = make_float4(0.f, 0.f, 0.f, 0.f);
        float sq = 0.f;
#pragma unroll
        for (int r = 0; r < 4; ++r) {        // 4 independent LDG.128
            float4 v = *reinterpret_cast<const float4*>(
                proto + (row0 + r) * D_DIM + c4 * 4);
            s.x += v.x; s.y += v.y; s.z += v.z; s.w += v.w;
            sq  += v.x * v.x + v.y * v.y + v.z * v.z + v.w * v.w;
        }
        *reinterpret_cast<float4*>(&sm_grp[g * D_DIM + c4 * 4]) = s;

#pragma unroll
        for (int o = 16; o > 0; o >>= 1)
            sq += __shfl_down_sync(0xFFFFFFFFu, sq, o);
        if (lane == 0) sm_p2g[warp] = sq;
        __syncthreads();

        g_partial[blk * D_DIM + tid] =
            sm_grp[tid] + sm_grp[D_DIM + tid] +
            sm_grp[2 * D_DIM + tid] + sm_grp[3 * D_DIM + tid];
        if (tid == 0) {
            float p2 = 0.f;
#pragma unroll
            for (int i = 0; i < NWARP; ++i) p2 += sm_p2g[i];
            g_p2[blk] = p2;
        }

        // R6 race fix: EVERY thread fences its own global store before the
        // block's arrival is published.
        __threadfence();
        __syncthreads();
        if (tid == 0)
            atomicAdd(&g_count, 1u);
    }

    // ---- Grid barrier: acquire-load spin on the arrival counter --------------
    if (tid == 0) {
        while (ld_acq_u32(&g_count) < NPART) { }
    }
    __syncthreads();

    // ---- Combine (every block, redundant; L2-resident 66KB, proven cheap) ----
    {
        const int c4 = tid & 63;
        const int g  = tid >> 6;
        float4 s = make_float4(0.f, 0.f, 0.f, 0.f);
#pragma unroll
        for (int i = 0; i < NPART / 4; ++i) {   // 16 partial rows per group
            const float4* p4 = reinterpret_cast<const float4*>(
                &g_partial[(g * (NPART / 4) + i) * D_DIM + c4 * 4]);
            float4 v = __ldcg(p4);
            s.x += v.x; s.y += v.y; s.z += v.z; s.w += v.w;
        }
        *reinterpret_cast<float4*>(&sm_grp[g * D_DIM + c4 * 4]) = s;

        if (warp == 0) {                     // all 32 lanes participate (R5 fix)
            float v = __ldcg(&g_p2[lane]) + __ldcg(&g_p2[lane + 32]);
#pragma unroll
            for (int o = 16; o > 0; o >>= 1)
                v += __shfl_down_sync(0xFFFFFFFFu, v, o);
            if (lane == 0) sm_c = v * (1.0f / (float)P_ROWS);
        }
        __syncthreads();

        float m = sm_grp[tid] + sm_grp[D_DIM + tid] +
                  sm_grp[2 * D_DIM + tid] + sm_grp[3 * D_DIM + tid];
        sm_m2[tid] = m * (2.0f / (float)P_ROWS);
        __syncthreads();
    }

    // ---- Phase 3: stream inputs, warp per row (grid-strided, as R3) ----------
    const float c  = sm_c;
    const int  d0  = lane * 8;
    const float4 m0 = *reinterpret_cast<const float4*>(&sm_m2[d0]);
    const float4 m1 = *reinterpret_cast<const float4*>(&sm_m2[d0 + 4]);
    const int gw = blk * NWARP + warp;       // global warp id, 0..4735

    for (int row = gw; row < B_ROWS; row += GRID * NWARP) {
        const float4* xr = reinterpret_cast<const float4*>(x + row * D_DIM + d0);
        float4 x0 = xr[0];
        float4 x1 = xr[1];

        float acc;
        acc  = x0.x * (x0.x - m0.x);
        acc += x0.y * (x0.y - m0.y);
        acc += x0.z * (x0.z - m0.z);
        acc += x0.w * (x0.w - m0.w);
        acc += x1.x * (x1.x - m1.x);
        acc += x1.y * (x1.y - m1.y);
        acc += x1.z * (x1.z - m1.z);
        acc += x1.w * (x1.w - m1.w);

#pragma unroll
        for (int o = 16; o > 0; o >>= 1)
            acc += __shfl_down_sync(0xFFFFFFFFu, acc, o);

        if (lane == 0) out[row] = acc + c;
    }

    // ---- Replay-state reset (R3's exit pass; measured harmless) --------------
    __syncthreads();
    if (tid == 0) {
        unsigned int d = atomicAdd(&g_done, 1u);
        if (d == GRID - 1) {                 // last block out resets everything
            g_count = 0;
            g_done  = 0;
            __threadfence();
        }
    }
}

extern "C" void kernel_launch(void* const* d_in, const int* in_sizes, int n_in,
                              void* d_out, int out_size) {
    const float* x     = (const float*)d_in[0];  // (8192, 256) float32
    const float* proto = (const float*)d_in[1];  // (1024, 256) float32
    float* out = (float*)d_out;                  // (8192,) float32

    som_fused<<<GRID, 256>>>(x, proto, out);
}